// round 6
// baseline (speedup 1.0000x reference)
#include <cuda_runtime.h>
#include <cuda_fp16.h>
#include <math.h>
#include <stdint.h>

// ================= problem constants =================
namespace {
constexpr int B_ = 8, L_ = 4800, D_ = 256, H_ = 8, DIM_ = 32;
constexpr int M_ = B_ * L_;            // 38400 rows
constexpr float EPS_ATTN = 1e-6f, EPS_LN = 1e-5f;
constexpr int KV_ELEMS = B_ * H_ * DIM_ * DIM_;   // 65536
constexpr int KS_ELEMS = B_ * H_ * DIM_;          // 2048

// GEMM tile: CTA 64x256, BK=32, 8 warps, warp tile 64x32
constexpr int BM = 64;
constexpr int BSTAGES = 6;                     // B cp.async ring stages
// smem (float units): A ring 2x1024 u32, B ring 6x4096 u32, params 768 f
constexpr int AS_U32 = 2048;
constexpr int BS_U32 = BSTAGES * 4096;         // 24576
constexpr int PRM_F  = AS_U32 + BS_U32;        // 26624
constexpr int SMEM_FLOATS = PRM_F + 768;       // 27392
constexpr int SMEM_BYTES = SMEM_FLOATS * 4;    // 109568
}

// ================= scratch (static device globals) =================
__device__ float g_x0[M_ * D_];
__device__ float g_x1[M_ * D_];
__device__ float g_Q [M_ * D_];
__device__ float g_K [M_ * D_];
__device__ float g_V [M_ * D_];
__device__ float g_A [M_ * D_];
__device__ float g_Msg[M_ * D_];
__device__ float g_Hid[M_ * 2 * D_];
__device__ float g_KV[KV_ELEMS];
__device__ float g_Ks[KS_ELEMS];
__device__ __half g_WTh [4 * D_ * D_];        // packed frag-major fp16 weights
__device__ __half g_w1Th[8 * 2 * D_ * D_];
__device__ __half g_w2Th[8 * D_ * 2 * D_];

// ================= mma helper =================
__device__ __forceinline__ void mma_f16(float d[4], const uint32_t a[4],
                                        uint32_t b0, uint32_t b1) {
    asm volatile(
        "mma.sync.aligned.m16n8k16.row.col.f32.f16.f16.f32 "
        "{%0,%1,%2,%3}, {%4,%5,%6,%7}, {%8,%9}, {%0,%1,%2,%3};\n"
        : "+f"(d[0]), "+f"(d[1]), "+f"(d[2]), "+f"(d[3])
        : "r"(a[0]), "r"(a[1]), "r"(a[2]), "r"(a[3]), "r"(b0), "r"(b1));
}

// ================= weight pack: [K,N] f32 -> fragment-major fp16 =================
__device__ __forceinline__ void pack_one(const float* __restrict__ in,
                                         __half* __restrict__ out,
                                         int t, int K, int N)
{
    int k = t / N, n = t % N;
    int nblk = n >> 8, nloc = n & 255;
    int wn = nloc >> 5, j = (nloc >> 3) & 3, gid = nloc & 7;
    int p = j >> 1, jh = j & 1;
    int kch = k >> 5, c16 = k & 15, kstep = (k >> 4) & 1;
    int qid = (c16 >> 1) & 3, kh = (c16 >> 3) & 1, h = c16 & 1;
    int NKCH = K >> 5;
    size_t idx = ((((((size_t)nblk * NKCH + kch) * 2 + kstep) * 8 + wn) * 2 + p) * 32
                  + qid * 8 + gid) * 8 + jh * 4 + kh * 2 + h;
    out[idx] = __float2half_rn(in[t]);
}

// one kernel packs everything: QKVM (4x64K), w1 (8x128K), w2 (8x128K)
__global__ void pack_all(const float* __restrict__ Wq, const float* __restrict__ Wk,
                         const float* __restrict__ Wv, const float* __restrict__ Wm,
                         const float* __restrict__ w1, const float* __restrict__ w2,
                         __half* __restrict__ WTh, __half* __restrict__ w1Th,
                         __half* __restrict__ w2Th)
{
    long idx = (long)blockIdx.x * 256 + threadIdx.x;
    const long S0 = 4L * 65536, S1 = 8L * 131072;
    if (idx < S0) {
        int which = (int)(idx >> 16), t = (int)(idx & 65535);
        const float* src = which == 0 ? Wq : which == 1 ? Wk : which == 2 ? Wv : Wm;
        pack_one(src, WTh + (long)which * 65536, t, 256, 256);
    } else if (idx < S0 + S1) {
        long i2 = idx - S0;
        int layer = (int)(i2 >> 17), t = (int)(i2 & 131071);
        pack_one(w1 + (long)layer * 131072, w1Th + (long)layer * 131072, t, 256, 512);
    } else {
        long i2 = idx - S0 - S1;
        int layer = (int)(i2 >> 17), t = (int)(i2 & 131071);
        pack_one(w2 + (long)layer * 131072, w2Th + (long)layer * 131072, t, 512, 256);
    }
}

// ================= fp16 tensor-core GEMM, deep cp.async pipeline =================
enum { EPI_QK = 1, EPI_V = 2, EPI_RELU = 3, EPI_BIAS_LN = 5, EPI_LN_RES = 6 };

#define WAITG(n) do {                                                          \
    switch (n) {                                                               \
    case 4: asm volatile("cp.async.wait_group 4;" ::: "memory"); break;        \
    case 3: asm volatile("cp.async.wait_group 3;" ::: "memory"); break;        \
    case 2: asm volatile("cp.async.wait_group 2;" ::: "memory"); break;        \
    case 1: asm volatile("cp.async.wait_group 1;" ::: "memory"); break;        \
    default: asm volatile("cp.async.wait_group 0;" ::: "memory"); break;       \
    } } while (0)

template<int EPI>
__global__ __launch_bounds__(256, 2)
void gemm_f16(const float* __restrict__ A, const __half* __restrict__ Bp,
              const float* __restrict__ bias, const float* __restrict__ mask,
              const float* __restrict__ lng, const float* __restrict__ lnb,
              float* __restrict__ C, int N, int K)
{
    extern __shared__ float sm[];
    uint32_t* As = (uint32_t*)sm;                 // 2 slots x 1024 u32
    uint32_t* Bs = (uint32_t*)sm + AS_U32;        // 6 slots x 4096 u32
    float* sbias = sm + PRM_F;
    float* sg    = sbias + 256;
    float* sb    = sg + 256;
    float* red1 = sm;                // epilogue scratch (reuses A ring)
    float* red2 = sm + 512;
    float* smu  = sm + 1024;
    float* srs  = sm + 1088;

    const int tid = threadIdx.x;
    const int wn = tid >> 5, lane = tid & 31;
    const int gid = lane >> 2, qid = lane & 3;
    const int rowBase = blockIdx.y * BM;
    const int colBase = blockIdx.x * 256;
    const int NKCH = K >> 5;

    if (EPI == EPI_QK || EPI == EPI_V || EPI == EPI_BIAS_LN)
        sbias[tid] = bias[colBase + tid];
    if (EPI == EPI_BIAS_LN || EPI == EPI_LN_RES) { sg[tid] = lng[tid]; sb[tid] = lnb[tid]; }

    const uint32_t sm_b = (uint32_t)__cvta_generic_to_shared(sm);

    // ---- A staging: coalesced (warp = 8 rows x 128B) ----
    const int arow = tid >> 2, aq = tid & 3;               // row 0..63, col quad
    const float* Aptr = A + (size_t)(rowBase + arow) * K + aq * 8;
    const int a_sts = ((aq >> 1) * 4 + (arow >> 4)) * 128 + (arow & 7) * 4
                    + (aq & 1) * 2 + ((arow >> 3) & 1);
    float4 abuf[2][2];

    #define LDG_A(c, bi)                                                        \
        do { abuf[bi][0] = *(const float4*)(Aptr + (size_t)(c) * 32);           \
             abuf[bi][1] = *(const float4*)(Aptr + (size_t)(c) * 32 + 4);       \
        } while (0)

    #define STS_A(sl, bi)                                                       \
        do { uint32_t* _d = As + (sl) * 1024;                                    \
            const float* _f = (const float*)abuf[bi];                            \
            _Pragma("unroll")                                                    \
            for (int _q = 0; _q < 4; _q++) {                                     \
                __half2 _h = __float22half2_rn(make_float2(_f[2*_q], _f[2*_q+1])); \
                _d[a_sts + _q * 32] = *(const uint32_t*)&_h;                      \
            }                                                                     \
        } while (0)

    #define LDG_B(c, sl)                                                         \
        do { uint32_t _dst = sm_b + (AS_U32 + (sl) * 4096) * 4 + tid * 16;        \
            const __half* _src = Bp + (((size_t)blockIdx.x * NKCH + (c)) << 13) + tid * 8; \
            _Pragma("unroll")                                                     \
            for (int _it = 0; _it < 4; _it++)                                     \
                asm volatile("cp.async.cg.shared.global [%0], [%1], 16;"          \
                             :: "r"(_dst + _it * 4096), "l"(_src + _it * 2048));  \
            asm volatile("cp.async.commit_group;");                               \
        } while (0)

    float acc[4][4][4];
    #pragma unroll
    for (int mi = 0; mi < 4; mi++)
        #pragma unroll
        for (int j = 0; j < 4; j++)
            #pragma unroll
            for (int q = 0; q < 4; q++) acc[mi][j][q] = 0.f;

    // ---- prologue: 5 B chunks in flight, A chunk 0 staged, chunk 1 in regs ----
    LDG_B(0, 0); LDG_B(1, 1); LDG_B(2, 2); LDG_B(3, 3); LDG_B(4, 4);
    LDG_A(0, 0); STS_A(0, 0);
    LDG_A(1, 1);

    const int fragoff = (qid * 8 + gid) * 4;
    int cs = 0;   // compute slot = k % 6
    for (int k = 0; k < NKCH; k++) {
        int ahead = NKCH - 1 - k; if (ahead > 4) ahead = 4;
        WAITG(ahead);            // B_k complete (own groups)
        __syncthreads();         // cross-thread visibility + closes compute k-1

        if (k + 5 < NKCH) { int isl = cs == 0 ? 5 : cs - 1; LDG_B(k + 5, isl); }
        if (k + 2 < NKCH) LDG_A(k + 2, k & 1);
        if (k + 1 < NKCH) STS_A((k + 1) & 1, (k + 1) & 1);

        const uint32_t* as = As + (k & 1) * 1024;
        const uint32_t* bs = Bs + cs * 4096;
        #pragma unroll
        for (int kst = 0; kst < 2; kst++) {
            uint4 af[4], bf[2];
            #pragma unroll
            for (int mi = 0; mi < 4; mi++)
                af[mi] = *(const uint4*)(as + (kst * 4 + mi) * 128 + fragoff);
            #pragma unroll
            for (int p = 0; p < 2; p++)
                bf[p] = *(const uint4*)(bs + ((kst * 8 + wn) * 2 + p) * 128 + fragoff);
            #pragma unroll
            for (int mi = 0; mi < 4; mi++) {
                const uint32_t a4[4] = {af[mi].x, af[mi].y, af[mi].z, af[mi].w};
                mma_f16(acc[mi][0], a4, bf[0].x, bf[0].y);
                mma_f16(acc[mi][1], a4, bf[0].z, bf[0].w);
                mma_f16(acc[mi][2], a4, bf[1].x, bf[1].y);
                mma_f16(acc[mi][3], a4, bf[1].z, bf[1].w);
            }
        }
        cs = (cs + 1 == BSTAGES) ? 0 : cs + 1;
    }
    __syncthreads();   // staging smem free for epilogue scratch

    // ================= epilogue =================
    // element (mi,j,q): row = rowBase + mi*16 + (q>>1)*8 + gid
    //                   col = colBase + wn*32 + j*8 + qid*2 + (q&1)
    if (EPI == EPI_QK || EPI == EPI_V || EPI == EPI_BIAS_LN) {
        #pragma unroll
        for (int mi = 0; mi < 4; mi++)
            #pragma unroll
            for (int j = 0; j < 4; j++) {
                const int c = wn * 32 + j * 8 + qid * 2;
                acc[mi][j][0] += sbias[c];   acc[mi][j][1] += sbias[c + 1];
                acc[mi][j][2] += sbias[c];   acc[mi][j][3] += sbias[c + 1];
            }
    }
    if (EPI == EPI_QK || EPI == EPI_V) {
        float mk[4][2];
        #pragma unroll
        for (int mi = 0; mi < 4; mi++)
            #pragma unroll
            for (int r = 0; r < 2; r++)
                mk[mi][r] = mask[rowBase + mi * 16 + r * 8 + gid];
        #pragma unroll
        for (int mi = 0; mi < 4; mi++)
            #pragma unroll
            for (int j = 0; j < 4; j++)
                #pragma unroll
                for (int q = 0; q < 4; q++) {
                    float t = acc[mi][j][q];
                    if (EPI == EPI_QK) t = (t > 0.f) ? (t + 1.f) : expf(t);
                    acc[mi][j][q] = t * mk[mi][q >> 1];
                }
    }
    if (EPI == EPI_RELU) {
        #pragma unroll
        for (int mi = 0; mi < 4; mi++)
            #pragma unroll
            for (int j = 0; j < 4; j++)
                #pragma unroll
                for (int q = 0; q < 4; q++)
                    acc[mi][j][q] = acc[mi][j][q] > 0.f ? acc[mi][j][q] : 0.f;
    }

    if (EPI == EPI_BIAS_LN || EPI == EPI_LN_RES) {
        float s1[4][2], s2[4][2];
        #pragma unroll
        for (int mi = 0; mi < 4; mi++)
            #pragma unroll
            for (int r = 0; r < 2; r++) { s1[mi][r] = 0.f; s2[mi][r] = 0.f; }
        #pragma unroll
        for (int mi = 0; mi < 4; mi++)
            #pragma unroll
            for (int j = 0; j < 4; j++)
                #pragma unroll
                for (int q = 0; q < 4; q++) {
                    float v = acc[mi][j][q];
                    s1[mi][q >> 1] += v;
                    s2[mi][q >> 1] = fmaf(v, v, s2[mi][q >> 1]);
                }
        #pragma unroll
        for (int o = 1; o <= 2; o <<= 1)
            #pragma unroll
            for (int mi = 0; mi < 4; mi++)
                #pragma unroll
                for (int r = 0; r < 2; r++) {
                    s1[mi][r] += __shfl_xor_sync(0xffffffffu, s1[mi][r], o);
                    s2[mi][r] += __shfl_xor_sync(0xffffffffu, s2[mi][r], o);
                }
        if (qid == 0) {
            #pragma unroll
            for (int mi = 0; mi < 4; mi++)
                #pragma unroll
                for (int r = 0; r < 2; r++) {
                    int rl = mi * 16 + r * 8 + gid;
                    red1[rl * 8 + wn] = s1[mi][r];
                    red2[rl * 8 + wn] = s2[mi][r];
                }
        }
        __syncthreads();
        if (tid < 64) {
            float a = 0.f, b2 = 0.f;
            #pragma unroll
            for (int w = 0; w < 8; w++) { a += red1[tid * 8 + w]; b2 += red2[tid * 8 + w]; }
            float mu = a * (1.f / 256.f);
            float var = b2 * (1.f / 256.f) - mu * mu;
            smu[tid] = mu;
            srs[tid] = rsqrtf(var + EPS_LN);
        }
        __syncthreads();
        #pragma unroll
        for (int mi = 0; mi < 4; mi++)
            #pragma unroll
            for (int j = 0; j < 4; j++)
                #pragma unroll
                for (int q = 0; q < 4; q++) {
                    int rl = mi * 16 + (q >> 1) * 8 + gid;
                    int c  = wn * 32 + j * 8 + qid * 2 + (q & 1);
                    acc[mi][j][q] = (acc[mi][j][q] - smu[rl]) * srs[rl] * sg[c] + sb[c];
                }
    }

    // store
    #pragma unroll
    for (int mi = 0; mi < 4; mi++) {
        #pragma unroll
        for (int j = 0; j < 4; j++) {
            const int c  = colBase + wn * 32 + j * 8 + qid * 2;
            const int r0 = rowBase + mi * 16 + gid;
            const int r1 = r0 + 8;
            float2 v0 = make_float2(acc[mi][j][0], acc[mi][j][1]);
            float2 v1 = make_float2(acc[mi][j][2], acc[mi][j][3]);
            if (EPI == EPI_LN_RES) {
                float2 x0 = *(const float2*)&C[(size_t)r0 * N + c];
                float2 x1 = *(const float2*)&C[(size_t)r1 * N + c];
                v0.x += x0.x; v0.y += x0.y;
                v1.x += x1.x; v1.y += x1.y;
            }
            *(float2*)&C[(size_t)r0 * N + c] = v0;
            *(float2*)&C[(size_t)r1 * N + c] = v1;
        }
    }
    #undef LDG_A
    #undef STS_A
    #undef LDG_B
}

// ================= zero KV / Ksum =================
__global__ void zero_kv(float* __restrict__ kv, float* __restrict__ ks)
{
    int i = blockIdx.x * 256 + threadIdx.x;
    if (i < KV_ELEMS) kv[i] = 0.f;
    if (i < KS_ELEMS) ks[i] = 0.f;
}

// ================= KV reduction =================
__global__ __launch_bounds__(256)
void kv_kernel(const float* __restrict__ Kp, const float* __restrict__ Vp,
               float* __restrict__ KV, float* __restrict__ Ks, int rowsPerSplit)
{
    const int bh = blockIdx.x;
    const int b = bh >> 3, h = bh & 7;
    const int l0 = blockIdx.y * rowsPerSplit;
    const int tid = threadIdx.x;
    const int lr = tid >> 5;
    const int ld = tid & 31;

    __shared__ float Kt[8][32];
    __shared__ float Vt[8][32];

    float a0 = 0.f, a1 = 0.f, a2 = 0.f, a3 = 0.f, ks = 0.f;

    for (int c = 0; c < rowsPerSplit; c += 8) {
        int l = l0 + c + lr;
        size_t base = ((size_t)b * L_ + l) * D_ + h * DIM_ + ld;
        Kt[lr][ld] = Kp[base];
        Vt[lr][ld] = Vp[base];
        __syncthreads();
        #pragma unroll
        for (int r = 0; r < 8; r++) {
            float kv = Kt[r][ld];
            a0 = fmaf(kv, Vt[r][lr +  0], a0);
            a1 = fmaf(kv, Vt[r][lr +  8], a1);
            a2 = fmaf(kv, Vt[r][lr + 16], a2);
            a3 = fmaf(kv, Vt[r][lr + 24], a3);
        }
        if (tid < 32) {
            #pragma unroll
            for (int r = 0; r < 8; r++) ks += Kt[r][tid];
        }
        __syncthreads();
    }

    float* kvb = KV + (size_t)bh * DIM_ * DIM_;
    atomicAdd(&kvb[(lr +  0) * DIM_ + ld], a0);
    atomicAdd(&kvb[(lr +  8) * DIM_ + ld], a1);
    atomicAdd(&kvb[(lr + 16) * DIM_ + ld], a2);
    atomicAdd(&kvb[(lr + 24) * DIM_ + ld], a3);
    if (tid < 32) atomicAdd(&Ks[bh * DIM_ + tid], ks);
}

// ================= attention apply =================
__global__ __launch_bounds__(256)
void attn_apply(const float* __restrict__ Q, const float* __restrict__ KV,
                const float* __restrict__ Ks, float* __restrict__ Out)
{
    __shared__ float sKV[H_ * DIM_ * DIM_];
    __shared__ float sKs[H_ * DIM_];
    const int b = blockIdx.y;
    const int tid = threadIdx.x;

    for (int i = tid; i < H_ * DIM_ * DIM_; i += 256)
        sKV[i] = KV[(size_t)b * H_ * DIM_ * DIM_ + i];
    if (tid < H_ * DIM_) sKs[tid] = Ks[b * H_ * DIM_ + tid];
    __syncthreads();

    const int token = blockIdx.x * 256 + tid;
    if (token >= L_) return;
    const size_t row = (size_t)b * L_ + token;
    const float* q = Q + row * D_;
    float* o = Out + row * D_;

    for (int h = 0; h < H_; h++) {
        float qr[DIM_];
        #pragma unroll
        for (int d = 0; d < DIM_; d++) qr[d] = q[h * DIM_ + d];
        float s = 0.f;
        #pragma unroll
        for (int d = 0; d < DIM_; d++) s = fmaf(qr[d], sKs[h * DIM_ + d], s);
        float z = 1.f / (s + EPS_ATTN);
        const float* kvh = &sKV[h * DIM_ * DIM_];
        #pragma unroll 4
        for (int m = 0; m < DIM_; m++) {
            float acc = 0.f;
            #pragma unroll
            for (int d = 0; d < DIM_; d++) acc = fmaf(kvh[m * DIM_ + d], qr[d], acc);
            o[h * DIM_ + m] = acc * z;
        }
    }
}

// ================= host orchestration =================
namespace {

struct Ptrs {
    float *x0, *x1, *Q, *K, *V, *A, *Msg, *Hid, *KV, *Ks;
    __half *WTh, *w1Th, *w2Th;
};

void run_layer(float* x, const float* src, const float* xm, const float* sm,
               const __half* WqP, const float* bq, const __half* WkP, const float* bk,
               const __half* WvP, const float* bv, const __half* WmP, const float* bm,
               const __half* w1P, const __half* w2P, const float* g1, const float* b1,
               const float* g2, const float* b2, const Ptrs& p)
{
    dim3 g1d(1, M_ / BM);   // (1, 600)
    dim3 g2d(2, M_ / BM);   // (2, 600)

    zero_kv<<<(KV_ELEMS + 255) / 256, 256>>>(p.KV, p.Ks);
    gemm_f16<EPI_QK><<<g1d, 256, SMEM_BYTES>>>(x,   WqP, bq, xm, nullptr, nullptr, p.Q, 256, 256);
    gemm_f16<EPI_QK><<<g1d, 256, SMEM_BYTES>>>(src, WkP, bk, sm, nullptr, nullptr, p.K, 256, 256);
    gemm_f16<EPI_V ><<<g1d, 256, SMEM_BYTES>>>(src, WvP, bv, sm, nullptr, nullptr, p.V, 256, 256);
    kv_kernel<<<dim3(B_ * H_, 20), 256>>>(p.K, p.V, p.KV, p.Ks, L_ / 20);
    attn_apply<<<dim3((L_ + 255) / 256, B_), 256>>>(p.Q, p.KV, p.Ks, p.A);

    gemm_f16<EPI_BIAS_LN><<<g1d, 256, SMEM_BYTES>>>(p.A,   WmP, bm, nullptr, g1, b1, p.Msg, 256, 256);
    gemm_f16<EPI_RELU  ><<<g2d, 256, SMEM_BYTES>>>(p.Msg, w1P, nullptr, nullptr, nullptr, nullptr, p.Hid, 512, 256);
    gemm_f16<EPI_LN_RES><<<g1d, 256, SMEM_BYTES>>>(p.Hid, w2P, nullptr, nullptr, g2, b2, x, 256, 512);
}

} // namespace

extern "C" void kernel_launch(void* const* d_in, const int* in_sizes, int n_in,
                              void* d_out, int out_size)
{
    const float* desc0 = (const float*)d_in[0];
    const float* desc1 = (const float*)d_in[1];
    const float* mask0 = (const float*)d_in[2];
    const float* mask1 = (const float*)d_in[3];
    const float* Wq = (const float*)d_in[4];
    const float* bq = (const float*)d_in[5];
    const float* Wk = (const float*)d_in[6];
    const float* bk = (const float*)d_in[7];
    const float* Wv = (const float*)d_in[8];
    const float* bv = (const float*)d_in[9];
    const float* Wm = (const float*)d_in[10];
    const float* bm = (const float*)d_in[11];
    const float* w1 = (const float*)d_in[12];
    const float* w2 = (const float*)d_in[13];
    const float* g1 = (const float*)d_in[14];
    const float* b1 = (const float*)d_in[15];
    const float* g2 = (const float*)d_in[16];
    const float* b2 = (const float*)d_in[17];

    Ptrs p;
    cudaGetSymbolAddress((void**)&p.x0,  g_x0);
    cudaGetSymbolAddress((void**)&p.x1,  g_x1);
    cudaGetSymbolAddress((void**)&p.Q,   g_Q);
    cudaGetSymbolAddress((void**)&p.K,   g_K);
    cudaGetSymbolAddress((void**)&p.V,   g_V);
    cudaGetSymbolAddress((void**)&p.A,   g_A);
    cudaGetSymbolAddress((void**)&p.Msg, g_Msg);
    cudaGetSymbolAddress((void**)&p.Hid, g_Hid);
    cudaGetSymbolAddress((void**)&p.KV,  g_KV);
    cudaGetSymbolAddress((void**)&p.Ks,  g_Ks);
    cudaGetSymbolAddress((void**)&p.WTh,  g_WTh);
    cudaGetSymbolAddress((void**)&p.w1Th, g_w1Th);
    cudaGetSymbolAddress((void**)&p.w2Th, g_w2Th);

    cudaFuncSetAttribute((const void*)gemm_f16<EPI_QK>,      cudaFuncAttributeMaxDynamicSharedMemorySize, SMEM_BYTES);
    cudaFuncSetAttribute((const void*)gemm_f16<EPI_V>,       cudaFuncAttributeMaxDynamicSharedMemorySize, SMEM_BYTES);
    cudaFuncSetAttribute((const void*)gemm_f16<EPI_RELU>,    cudaFuncAttributeMaxDynamicSharedMemorySize, SMEM_BYTES);
    cudaFuncSetAttribute((const void*)gemm_f16<EPI_BIAS_LN>, cudaFuncAttributeMaxDynamicSharedMemorySize, SMEM_BYTES);
    cudaFuncSetAttribute((const void*)gemm_f16<EPI_LN_RES>,  cudaFuncAttributeMaxDynamicSharedMemorySize, SMEM_BYTES);

    // ---- one-time prep (pack is a single launch so GEMMs land early for ncu) ----
    pack_all<<<(4 * 65536 + 2 * 8 * 131072) / 256, 256>>>(Wq, Wk, Wv, Wm, w1, w2,
                                                          p.WTh, p.w1Th, p.w2Th);

    const size_t tensorBytes = (size_t)M_ * D_ * sizeof(float);
    cudaMemcpyAsync(p.x0, desc0, tensorBytes, cudaMemcpyDeviceToDevice);
    cudaMemcpyAsync(p.x1, desc1, tensorBytes, cudaMemcpyDeviceToDevice);

    const int w1sz = D_ * 2 * D_;
    const int w2sz = 2 * D_ * D_;

    for (int li = 0; li < 8; li++) {
        const __half* lw1 = p.w1Th + (size_t)li * w1sz;
        const __half* lw2 = p.w2Th + (size_t)li * w2sz;
        const float* lg1 = g1 + li * D_;
        const float* lb1 = b1 + li * D_;
        const float* lg2 = g2 + li * D_;
        const float* lb2 = b2 + li * D_;
        const __half* WqP = p.WTh + 0 * D_ * D_;
        const __half* WkP = p.WTh + 1 * D_ * D_;
        const __half* WvP = p.WTh + 2 * D_ * D_;
        const __half* WmP = p.WTh + 3 * D_ * D_;
        if ((li & 1) == 0) {
            run_layer(p.x0, p.x0, mask0, mask0, WqP, bq, WkP, bk, WvP, bv, WmP, bm,
                      lw1, lw2, lg1, lb1, lg2, lb2, p);
            run_layer(p.x1, p.x1, mask1, mask1, WqP, bq, WkP, bk, WvP, bv, WmP, bm,
                      lw1, lw2, lg1, lb1, lg2, lb2, p);
        } else {
            run_layer(p.x0, p.x1, mask0, mask1, WqP, bq, WkP, bk, WvP, bv, WmP, bm,
                      lw1, lw2, lg1, lb1, lg2, lb2, p);
            run_layer(p.x1, p.x0, mask1, mask0, WqP, bq, WkP, bk, WvP, bv, WmP, bm,
                      lw1, lw2, lg1, lb1, lg2, lb2, p);
        }
    }

    cudaMemcpyAsync((float*)d_out,                   p.x0, tensorBytes, cudaMemcpyDeviceToDevice);
    cudaMemcpyAsync((float*)d_out + (size_t)M_ * D_, p.x1, tensorBytes, cudaMemcpyDeviceToDevice);
}

// round 7
// speedup vs baseline: 1.0467x; 1.0467x over previous
#include <cuda_runtime.h>
#include <cuda_fp16.h>
#include <math.h>
#include <stdint.h>

// ================= problem constants =================
namespace {
constexpr int B_ = 8, L_ = 4800, D_ = 256, H_ = 8, DIM_ = 32;
constexpr int M_ = B_ * L_;            // 38400 rows
constexpr float EPS_ATTN = 1e-6f, EPS_LN = 1e-5f;
constexpr int KV_ELEMS = B_ * H_ * DIM_ * DIM_;   // 65536
constexpr int KS_ELEMS = B_ * H_ * DIM_;          // 2048

// GEMM tile: CTA 64x256, BK=32, 8 warps, warp tile 64x32
constexpr int BM = 64;
constexpr int BSTAGES = 3;                     // B cp.async ring stages (occupancy!)
// smem (float units): A ring 2x1024 u32, B ring 3x4096 u32, params 768 f
constexpr int AS_U32 = 2048;
constexpr int BS_U32 = BSTAGES * 4096;         // 12288
constexpr int PRM_F  = AS_U32 + BS_U32;        // 14336
constexpr int SMEM_FLOATS = PRM_F + 768;       // 15104
constexpr int SMEM_BYTES = SMEM_FLOATS * 4;    // 60416  -> 2 CTAs/SM
}

// ================= scratch (static device globals) =================
__device__ float g_x0[M_ * D_];
__device__ float g_x1[M_ * D_];
__device__ float g_Q [M_ * D_];
__device__ float g_K [M_ * D_];
__device__ float g_V [M_ * D_];
__device__ float g_A [M_ * D_];
__device__ float g_Msg[M_ * D_];
__device__ float g_Hid[M_ * 2 * D_];
__device__ float g_KV[KV_ELEMS];
__device__ float g_Ks[KS_ELEMS];
__device__ __half g_WTh [4 * D_ * D_];        // packed frag-major fp16 weights
__device__ __half g_w1Th[8 * 2 * D_ * D_];
__device__ __half g_w2Th[8 * D_ * 2 * D_];

// ================= mma helper =================
__device__ __forceinline__ void mma_f16(float d[4], const uint32_t a[4],
                                        uint32_t b0, uint32_t b1) {
    asm volatile(
        "mma.sync.aligned.m16n8k16.row.col.f32.f16.f16.f32 "
        "{%0,%1,%2,%3}, {%4,%5,%6,%7}, {%8,%9}, {%0,%1,%2,%3};\n"
        : "+f"(d[0]), "+f"(d[1]), "+f"(d[2]), "+f"(d[3])
        : "r"(a[0]), "r"(a[1]), "r"(a[2]), "r"(a[3]), "r"(b0), "r"(b1));
}

// ================= weight pack: [K,N] f32 -> fragment-major fp16 =================
__device__ __forceinline__ void pack_one(const float* __restrict__ in,
                                         __half* __restrict__ out,
                                         int t, int K, int N)
{
    int k = t / N, n = t % N;
    int nblk = n >> 8, nloc = n & 255;
    int wn = nloc >> 5, j = (nloc >> 3) & 3, gid = nloc & 7;
    int p = j >> 1, jh = j & 1;
    int kch = k >> 5, c16 = k & 15, kstep = (k >> 4) & 1;
    int qid = (c16 >> 1) & 3, kh = (c16 >> 3) & 1, h = c16 & 1;
    int NKCH = K >> 5;
    size_t idx = ((((((size_t)nblk * NKCH + kch) * 2 + kstep) * 8 + wn) * 2 + p) * 32
                  + qid * 8 + gid) * 8 + jh * 4 + kh * 2 + h;
    out[idx] = __float2half_rn(in[t]);
}

// one kernel packs everything: QKVM (4x64K), w1 (8x128K), w2 (8x128K)
__global__ void pack_all(const float* __restrict__ Wq, const float* __restrict__ Wk,
                         const float* __restrict__ Wv, const float* __restrict__ Wm,
                         const float* __restrict__ w1, const float* __restrict__ w2,
                         __half* __restrict__ WTh, __half* __restrict__ w1Th,
                         __half* __restrict__ w2Th)
{
    long idx = (long)blockIdx.x * 256 + threadIdx.x;
    const long S0 = 4L * 65536, S1 = 8L * 131072;
    if (idx < S0) {
        int which = (int)(idx >> 16), t = (int)(idx & 65535);
        const float* src = which == 0 ? Wq : which == 1 ? Wk : which == 2 ? Wv : Wm;
        pack_one(src, WTh + (long)which * 65536, t, 256, 256);
    } else if (idx < S0 + S1) {
        long i2 = idx - S0;
        int layer = (int)(i2 >> 17), t = (int)(i2 & 131071);
        pack_one(w1 + (long)layer * 131072, w1Th + (long)layer * 131072, t, 256, 512);
    } else {
        long i2 = idx - S0 - S1;
        int layer = (int)(i2 >> 17), t = (int)(i2 & 131071);
        pack_one(w2 + (long)layer * 131072, w2Th + (long)layer * 131072, t, 512, 256);
    }
}

// ================= fp16 tensor-core GEMM =================
enum { EPI_QK = 1, EPI_V = 2, EPI_RELU = 3, EPI_BIAS_LN = 5, EPI_LN_RES = 6 };

template<int EPI>
__global__ __launch_bounds__(256, 2)
void gemm_f16(const float* __restrict__ A, const __half* __restrict__ Bp,
              const float* __restrict__ bias, const float* __restrict__ mask,
              const float* __restrict__ lng, const float* __restrict__ lnb,
              float* __restrict__ C, int N, int K)
{
    extern __shared__ float sm[];
    uint32_t* As = (uint32_t*)sm;                 // 2 slots x 1024 u32
    uint32_t* Bs = (uint32_t*)sm + AS_U32;        // 3 slots x 4096 u32
    float* sbias = sm + PRM_F;
    float* sg    = sbias + 256;
    float* sb    = sg + 256;
    float* red1 = sm;                // epilogue scratch (reuses A ring)
    float* red2 = sm + 512;
    float* smu  = sm + 1024;
    float* srs  = sm + 1088;

    const int tid = threadIdx.x;
    const int wn = tid >> 5, lane = tid & 31;
    const int gid = lane >> 2, qid = lane & 3;
    const int rowBase = blockIdx.y * BM;
    const int colBase = blockIdx.x * 256;
    const int NKCH = K >> 5;

    if (EPI == EPI_QK || EPI == EPI_V || EPI == EPI_BIAS_LN)
        sbias[tid] = bias[colBase + tid];
    if (EPI == EPI_BIAS_LN || EPI == EPI_LN_RES) { sg[tid] = lng[tid]; sb[tid] = lnb[tid]; }

    const uint32_t sm_b = (uint32_t)__cvta_generic_to_shared(sm);

    // ---- A staging: coalesced (warp = 8 rows x 128B) ----
    const int arow = tid >> 2, aq = tid & 3;               // row 0..63, col quad
    const float* Aptr = A + (size_t)(rowBase + arow) * K + aq * 8;
    const int a_sts = ((aq >> 1) * 4 + (arow >> 4)) * 128 + (arow & 7) * 4
                    + (aq & 1) * 2 + ((arow >> 3) & 1);
    float4 abuf[2][2];

    #define LDG_A(c, bi)                                                        \
        do { abuf[bi][0] = *(const float4*)(Aptr + (size_t)(c) * 32);           \
             abuf[bi][1] = *(const float4*)(Aptr + (size_t)(c) * 32 + 4);       \
        } while (0)

    #define STS_A(sl, bi)                                                       \
        do { uint32_t* _d = As + (sl) * 1024;                                    \
            const float* _f = (const float*)abuf[bi];                            \
            _Pragma("unroll")                                                    \
            for (int _q = 0; _q < 4; _q++) {                                     \
                __half2 _h = __float22half2_rn(make_float2(_f[2*_q], _f[2*_q+1])); \
                _d[a_sts + _q * 32] = *(const uint32_t*)&_h;                      \
            }                                                                     \
        } while (0)

    #define LDG_B(c, sl)                                                         \
        do { uint32_t _dst = sm_b + (AS_U32 + (sl) * 4096) * 4 + tid * 16;        \
            const __half* _src = Bp + (((size_t)blockIdx.x * NKCH + (c)) << 13) + tid * 8; \
            _Pragma("unroll")                                                     \
            for (int _it = 0; _it < 4; _it++)                                     \
                asm volatile("cp.async.cg.shared.global [%0], [%1], 16;"          \
                             :: "r"(_dst + _it * 4096), "l"(_src + _it * 2048));  \
            asm volatile("cp.async.commit_group;");                               \
        } while (0)

    float acc[4][4][4];
    #pragma unroll
    for (int mi = 0; mi < 4; mi++)
        #pragma unroll
        for (int j = 0; j < 4; j++)
            #pragma unroll
            for (int q = 0; q < 4; q++) acc[mi][j][q] = 0.f;

    // ---- prologue: 2 B chunks in flight, A chunk 0 staged, chunk 1 in regs ----
    LDG_B(0, 0); LDG_B(1, 1);
    LDG_A(0, 0); STS_A(0, 0);
    LDG_A(1, 1);

    const int fragoff = (qid * 8 + gid) * 4;
    int cs = 0;   // compute slot = k % 3
    for (int k = 0; k < NKCH; k++) {
        if (k + 1 < NKCH)
            asm volatile("cp.async.wait_group 1;" ::: "memory");
        else
            asm volatile("cp.async.wait_group 0;" ::: "memory");
        __syncthreads();         // B_k visible to all; closes compute k-1

        if (k + 2 < NKCH) { int isl = cs == 0 ? 2 : cs - 1; LDG_B(k + 2, isl); }
        if (k + 2 < NKCH) LDG_A(k + 2, k & 1);
        if (k + 1 < NKCH) STS_A((k + 1) & 1, (k + 1) & 1);

        const uint32_t* as = As + (k & 1) * 1024;
        const uint32_t* bs = Bs + cs * 4096;
        #pragma unroll
        for (int kst = 0; kst < 2; kst++) {
            uint4 af[4], bf[2];
            #pragma unroll
            for (int mi = 0; mi < 4; mi++)
                af[mi] = *(const uint4*)(as + (kst * 4 + mi) * 128 + fragoff);
            #pragma unroll
            for (int p = 0; p < 2; p++)
                bf[p] = *(const uint4*)(bs + ((kst * 8 + wn) * 2 + p) * 128 + fragoff);
            #pragma unroll
            for (int mi = 0; mi < 4; mi++) {
                const uint32_t a4[4] = {af[mi].x, af[mi].y, af[mi].z, af[mi].w};
                mma_f16(acc[mi][0], a4, bf[0].x, bf[0].y);
                mma_f16(acc[mi][1], a4, bf[0].z, bf[0].w);
                mma_f16(acc[mi][2], a4, bf[1].x, bf[1].y);
                mma_f16(acc[mi][3], a4, bf[1].z, bf[1].w);
            }
        }
        cs = (cs + 1 == BSTAGES) ? 0 : cs + 1;
    }
    __syncthreads();   // staging smem free for epilogue scratch

    // ================= epilogue =================
    // element (mi,j,q): row = rowBase + mi*16 + (q>>1)*8 + gid
    //                   col = colBase + wn*32 + j*8 + qid*2 + (q&1)
    if (EPI == EPI_QK || EPI == EPI_V || EPI == EPI_BIAS_LN) {
        #pragma unroll
        for (int mi = 0; mi < 4; mi++)
            #pragma unroll
            for (int j = 0; j < 4; j++) {
                const int c = wn * 32 + j * 8 + qid * 2;
                acc[mi][j][0] += sbias[c];   acc[mi][j][1] += sbias[c + 1];
                acc[mi][j][2] += sbias[c];   acc[mi][j][3] += sbias[c + 1];
            }
    }
    if (EPI == EPI_QK || EPI == EPI_V) {
        float mk[4][2];
        #pragma unroll
        for (int mi = 0; mi < 4; mi++)
            #pragma unroll
            for (int r = 0; r < 2; r++)
                mk[mi][r] = mask[rowBase + mi * 16 + r * 8 + gid];
        #pragma unroll
        for (int mi = 0; mi < 4; mi++)
            #pragma unroll
            for (int j = 0; j < 4; j++)
                #pragma unroll
                for (int q = 0; q < 4; q++) {
                    float t = acc[mi][j][q];
                    if (EPI == EPI_QK) t = (t > 0.f) ? (t + 1.f) : expf(t);
                    acc[mi][j][q] = t * mk[mi][q >> 1];
                }
    }
    if (EPI == EPI_RELU) {
        #pragma unroll
        for (int mi = 0; mi < 4; mi++)
            #pragma unroll
            for (int j = 0; j < 4; j++)
                #pragma unroll
                for (int q = 0; q < 4; q++)
                    acc[mi][j][q] = acc[mi][j][q] > 0.f ? acc[mi][j][q] : 0.f;
    }

    if (EPI == EPI_BIAS_LN || EPI == EPI_LN_RES) {
        float s1[4][2], s2[4][2];
        #pragma unroll
        for (int mi = 0; mi < 4; mi++)
            #pragma unroll
            for (int r = 0; r < 2; r++) { s1[mi][r] = 0.f; s2[mi][r] = 0.f; }
        #pragma unroll
        for (int mi = 0; mi < 4; mi++)
            #pragma unroll
            for (int j = 0; j < 4; j++)
                #pragma unroll
                for (int q = 0; q < 4; q++) {
                    float v = acc[mi][j][q];
                    s1[mi][q >> 1] += v;
                    s2[mi][q >> 1] = fmaf(v, v, s2[mi][q >> 1]);
                }
        #pragma unroll
        for (int o = 1; o <= 2; o <<= 1)
            #pragma unroll
            for (int mi = 0; mi < 4; mi++)
                #pragma unroll
                for (int r = 0; r < 2; r++) {
                    s1[mi][r] += __shfl_xor_sync(0xffffffffu, s1[mi][r], o);
                    s2[mi][r] += __shfl_xor_sync(0xffffffffu, s2[mi][r], o);
                }
        if (qid == 0) {
            #pragma unroll
            for (int mi = 0; mi < 4; mi++)
                #pragma unroll
                for (int r = 0; r < 2; r++) {
                    int rl = mi * 16 + r * 8 + gid;
                    red1[rl * 8 + wn] = s1[mi][r];
                    red2[rl * 8 + wn] = s2[mi][r];
                }
        }
        __syncthreads();
        if (tid < 64) {
            float a = 0.f, b2 = 0.f;
            #pragma unroll
            for (int w = 0; w < 8; w++) { a += red1[tid * 8 + w]; b2 += red2[tid * 8 + w]; }
            float mu = a * (1.f / 256.f);
            float var = b2 * (1.f / 256.f) - mu * mu;
            smu[tid] = mu;
            srs[tid] = rsqrtf(var + EPS_LN);
        }
        __syncthreads();
        #pragma unroll
        for (int mi = 0; mi < 4; mi++)
            #pragma unroll
            for (int j = 0; j < 4; j++)
                #pragma unroll
                for (int q = 0; q < 4; q++) {
                    int rl = mi * 16 + (q >> 1) * 8 + gid;
                    int c  = wn * 32 + j * 8 + qid * 2 + (q & 1);
                    acc[mi][j][q] = (acc[mi][j][q] - smu[rl]) * srs[rl] * sg[c] + sb[c];
                }
    }

    // store
    #pragma unroll
    for (int mi = 0; mi < 4; mi++) {
        #pragma unroll
        for (int j = 0; j < 4; j++) {
            const int c  = colBase + wn * 32 + j * 8 + qid * 2;
            const int r0 = rowBase + mi * 16 + gid;
            const int r1 = r0 + 8;
            float2 v0 = make_float2(acc[mi][j][0], acc[mi][j][1]);
            float2 v1 = make_float2(acc[mi][j][2], acc[mi][j][3]);
            if (EPI == EPI_LN_RES) {
                float2 x0 = *(const float2*)&C[(size_t)r0 * N + c];
                float2 x1 = *(const float2*)&C[(size_t)r1 * N + c];
                v0.x += x0.x; v0.y += x0.y;
                v1.x += x1.x; v1.y += x1.y;
            }
            *(float2*)&C[(size_t)r0 * N + c] = v0;
            *(float2*)&C[(size_t)r1 * N + c] = v1;
        }
    }
    #undef LDG_A
    #undef STS_A
    #undef LDG_B
}

// ================= zero KV / Ksum =================
__global__ void zero_kv(float* __restrict__ kv, float* __restrict__ ks)
{
    int i = blockIdx.x * 256 + threadIdx.x;
    if (i < KV_ELEMS) kv[i] = 0.f;
    if (i < KS_ELEMS) ks[i] = 0.f;
}

// ================= KV reduction =================
__global__ __launch_bounds__(256)
void kv_kernel(const float* __restrict__ Kp, const float* __restrict__ Vp,
               float* __restrict__ KV, float* __restrict__ Ks, int rowsPerSplit)
{
    const int bh = blockIdx.x;
    const int b = bh >> 3, h = bh & 7;
    const int l0 = blockIdx.y * rowsPerSplit;
    const int tid = threadIdx.x;
    const int lr = tid >> 5;
    const int ld = tid & 31;

    __shared__ float Kt[8][32];
    __shared__ float Vt[8][32];

    float a0 = 0.f, a1 = 0.f, a2 = 0.f, a3 = 0.f, ks = 0.f;

    for (int c = 0; c < rowsPerSplit; c += 8) {
        int l = l0 + c + lr;
        size_t base = ((size_t)b * L_ + l) * D_ + h * DIM_ + ld;
        Kt[lr][ld] = Kp[base];
        Vt[lr][ld] = Vp[base];
        __syncthreads();
        #pragma unroll
        for (int r = 0; r < 8; r++) {
            float kv = Kt[r][ld];
            a0 = fmaf(kv, Vt[r][lr +  0], a0);
            a1 = fmaf(kv, Vt[r][lr +  8], a1);
            a2 = fmaf(kv, Vt[r][lr + 16], a2);
            a3 = fmaf(kv, Vt[r][lr + 24], a3);
        }
        if (tid < 32) {
            #pragma unroll
            for (int r = 0; r < 8; r++) ks += Kt[r][tid];
        }
        __syncthreads();
    }

    float* kvb = KV + (size_t)bh * DIM_ * DIM_;
    atomicAdd(&kvb[(lr +  0) * DIM_ + ld], a0);
    atomicAdd(&kvb[(lr +  8) * DIM_ + ld], a1);
    atomicAdd(&kvb[(lr + 16) * DIM_ + ld], a2);
    atomicAdd(&kvb[(lr + 24) * DIM_ + ld], a3);
    if (tid < 32) atomicAdd(&Ks[bh * DIM_ + tid], ks);
}

// ================= attention apply =================
__global__ __launch_bounds__(256)
void attn_apply(const float* __restrict__ Q, const float* __restrict__ KV,
                const float* __restrict__ Ks, float* __restrict__ Out)
{
    __shared__ float sKV[H_ * DIM_ * DIM_];
    __shared__ float sKs[H_ * DIM_];
    const int b = blockIdx.y;
    const int tid = threadIdx.x;

    for (int i = tid; i < H_ * DIM_ * DIM_; i += 256)
        sKV[i] = KV[(size_t)b * H_ * DIM_ * DIM_ + i];
    if (tid < H_ * DIM_) sKs[tid] = Ks[b * H_ * DIM_ + tid];
    __syncthreads();

    const int token = blockIdx.x * 256 + tid;
    if (token >= L_) return;
    const size_t row = (size_t)b * L_ + token;
    const float* q = Q + row * D_;
    float* o = Out + row * D_;

    for (int h = 0; h < H_; h++) {
        float qr[DIM_];
        #pragma unroll
        for (int d = 0; d < DIM_; d++) qr[d] = q[h * DIM_ + d];
        float s = 0.f;
        #pragma unroll
        for (int d = 0; d < DIM_; d++) s = fmaf(qr[d], sKs[h * DIM_ + d], s);
        float z = 1.f / (s + EPS_ATTN);
        const float* kvh = &sKV[h * DIM_ * DIM_];
        #pragma unroll 4
        for (int m = 0; m < DIM_; m++) {
            float acc = 0.f;
            #pragma unroll
            for (int d = 0; d < DIM_; d++) acc = fmaf(kvh[m * DIM_ + d], qr[d], acc);
            o[h * DIM_ + m] = acc * z;
        }
    }
}

// ================= host orchestration =================
namespace {

struct Ptrs {
    float *x0, *x1, *Q, *K, *V, *A, *Msg, *Hid, *KV, *Ks;
    __half *WTh, *w1Th, *w2Th;
};

void run_layer(float* x, const float* src, const float* xm, const float* sm,
               const __half* WqP, const float* bq, const __half* WkP, const float* bk,
               const __half* WvP, const float* bv, const __half* WmP, const float* bm,
               const __half* w1P, const __half* w2P, const float* g1, const float* b1,
               const float* g2, const float* b2, const Ptrs& p)
{
    dim3 g1d(1, M_ / BM);   // (1, 600)
    dim3 g2d(2, M_ / BM);   // (2, 600)

    zero_kv<<<(KV_ELEMS + 255) / 256, 256>>>(p.KV, p.Ks);
    gemm_f16<EPI_QK><<<g1d, 256, SMEM_BYTES>>>(x,   WqP, bq, xm, nullptr, nullptr, p.Q, 256, 256);
    gemm_f16<EPI_QK><<<g1d, 256, SMEM_BYTES>>>(src, WkP, bk, sm, nullptr, nullptr, p.K, 256, 256);
    gemm_f16<EPI_V ><<<g1d, 256, SMEM_BYTES>>>(src, WvP, bv, sm, nullptr, nullptr, p.V, 256, 256);
    kv_kernel<<<dim3(B_ * H_, 20), 256>>>(p.K, p.V, p.KV, p.Ks, L_ / 20);
    attn_apply<<<dim3((L_ + 255) / 256, B_), 256>>>(p.Q, p.KV, p.Ks, p.A);

    gemm_f16<EPI_BIAS_LN><<<g1d, 256, SMEM_BYTES>>>(p.A,   WmP, bm, nullptr, g1, b1, p.Msg, 256, 256);
    gemm_f16<EPI_RELU  ><<<g2d, 256, SMEM_BYTES>>>(p.Msg, w1P, nullptr, nullptr, nullptr, nullptr, p.Hid, 512, 256);
    gemm_f16<EPI_LN_RES><<<g1d, 256, SMEM_BYTES>>>(p.Hid, w2P, nullptr, nullptr, g2, b2, x, 256, 512);
}

} // namespace

extern "C" void kernel_launch(void* const* d_in, const int* in_sizes, int n_in,
                              void* d_out, int out_size)
{
    const float* desc0 = (const float*)d_in[0];
    const float* desc1 = (const float*)d_in[1];
    const float* mask0 = (const float*)d_in[2];
    const float* mask1 = (const float*)d_in[3];
    const float* Wq = (const float*)d_in[4];
    const float* bq = (const float*)d_in[5];
    const float* Wk = (const float*)d_in[6];
    const float* bk = (const float*)d_in[7];
    const float* Wv = (const float*)d_in[8];
    const float* bv = (const float*)d_in[9];
    const float* Wm = (const float*)d_in[10];
    const float* bm = (const float*)d_in[11];
    const float* w1 = (const float*)d_in[12];
    const float* w2 = (const float*)d_in[13];
    const float* g1 = (const float*)d_in[14];
    const float* b1 = (const float*)d_in[15];
    const float* g2 = (const float*)d_in[16];
    const float* b2 = (const float*)d_in[17];

    Ptrs p;
    cudaGetSymbolAddress((void**)&p.x0,  g_x0);
    cudaGetSymbolAddress((void**)&p.x1,  g_x1);
    cudaGetSymbolAddress((void**)&p.Q,   g_Q);
    cudaGetSymbolAddress((void**)&p.K,   g_K);
    cudaGetSymbolAddress((void**)&p.V,   g_V);
    cudaGetSymbolAddress((void**)&p.A,   g_A);
    cudaGetSymbolAddress((void**)&p.Msg, g_Msg);
    cudaGetSymbolAddress((void**)&p.Hid, g_Hid);
    cudaGetSymbolAddress((void**)&p.KV,  g_KV);
    cudaGetSymbolAddress((void**)&p.Ks,  g_Ks);
    cudaGetSymbolAddress((void**)&p.WTh,  g_WTh);
    cudaGetSymbolAddress((void**)&p.w1Th, g_w1Th);
    cudaGetSymbolAddress((void**)&p.w2Th, g_w2Th);

    cudaFuncSetAttribute((const void*)gemm_f16<EPI_QK>,      cudaFuncAttributeMaxDynamicSharedMemorySize, SMEM_BYTES);
    cudaFuncSetAttribute((const void*)gemm_f16<EPI_V>,       cudaFuncAttributeMaxDynamicSharedMemorySize, SMEM_BYTES);
    cudaFuncSetAttribute((const void*)gemm_f16<EPI_RELU>,    cudaFuncAttributeMaxDynamicSharedMemorySize, SMEM_BYTES);
    cudaFuncSetAttribute((const void*)gemm_f16<EPI_BIAS_LN>, cudaFuncAttributeMaxDynamicSharedMemorySize, SMEM_BYTES);
    cudaFuncSetAttribute((const void*)gemm_f16<EPI_LN_RES>,  cudaFuncAttributeMaxDynamicSharedMemorySize, SMEM_BYTES);

    // ---- one-time prep ----
    pack_all<<<(4 * 65536 + 2 * 8 * 131072) / 256, 256>>>(Wq, Wk, Wv, Wm, w1, w2,
                                                          p.WTh, p.w1Th, p.w2Th);

    const size_t tensorBytes = (size_t)M_ * D_ * sizeof(float);
    cudaMemcpyAsync(p.x0, desc0, tensorBytes, cudaMemcpyDeviceToDevice);
    cudaMemcpyAsync(p.x1, desc1, tensorBytes, cudaMemcpyDeviceToDevice);

    const int w1sz = D_ * 2 * D_;
    const int w2sz = 2 * D_ * D_;

    for (int li = 0; li < 8; li++) {
        const __half* lw1 = p.w1Th + (size_t)li * w1sz;
        const __half* lw2 = p.w2Th + (size_t)li * w2sz;
        const float* lg1 = g1 + li * D_;
        const float* lb1 = b1 + li * D_;
        const float* lg2 = g2 + li * D_;
        const float* lb2 = b2 + li * D_;
        const __half* WqP = p.WTh + 0 * D_ * D_;
        const __half* WkP = p.WTh + 1 * D_ * D_;
        const __half* WvP = p.WTh + 2 * D_ * D_;
        const __half* WmP = p.WTh + 3 * D_ * D_;
        if ((li & 1) == 0) {
            run_layer(p.x0, p.x0, mask0, mask0, WqP, bq, WkP, bk, WvP, bv, WmP, bm,
                      lw1, lw2, lg1, lb1, lg2, lb2, p);
            run_layer(p.x1, p.x1, mask1, mask1, WqP, bq, WkP, bk, WvP, bv, WmP, bm,
                      lw1, lw2, lg1, lb1, lg2, lb2, p);
        } else {
            run_layer(p.x0, p.x1, mask0, mask1, WqP, bq, WkP, bk, WvP, bv, WmP, bm,
                      lw1, lw2, lg1, lb1, lg2, lb2, p);
            run_layer(p.x1, p.x0, mask1, mask0, WqP, bq, WkP, bk, WvP, bv, WmP, bm,
                      lw1, lw2, lg1, lb1, lg2, lb2, p);
        }
    }

    cudaMemcpyAsync((float*)d_out,                   p.x0, tensorBytes, cudaMemcpyDeviceToDevice);
    cudaMemcpyAsync((float*)d_out + (size_t)M_ * D_, p.x1, tensorBytes, cudaMemcpyDeviceToDevice);
}

// round 8
// speedup vs baseline: 1.5526x; 1.4833x over previous
#include <cuda_runtime.h>
#include <cuda_fp16.h>
#include <math.h>
#include <stdint.h>

// ================= problem constants =================
namespace {
constexpr int B_ = 8, L_ = 4800, D_ = 256, H_ = 8, DIM_ = 32;
constexpr int M_ = B_ * L_;            // 38400 rows
constexpr float EPS_ATTN = 1e-6f, EPS_LN = 1e-5f;
constexpr int KV_ELEMS = B_ * H_ * DIM_ * DIM_;   // 65536
constexpr int KS_ELEMS = B_ * H_ * DIM_;          // 2048

constexpr int BM = 64;                 // CTA rows; 8 warps; warp tile 64x32
// dynamic smem: A frags KCH*1024 u32 + params 768 f
constexpr int SMEM_K8  = (8  * 1024 + 768) * 4;   // 35840 B
constexpr int SMEM_K16 = (16 * 1024 + 768) * 4;   // 68608 B
}

// ================= scratch (static device globals) =================
__device__ float g_x0[M_ * D_];
__device__ float g_x1[M_ * D_];
__device__ float g_Q [M_ * D_];
__device__ float g_K [M_ * D_];
__device__ float g_V [M_ * D_];
__device__ float g_A [M_ * D_];
__device__ float g_Msg[M_ * D_];
__device__ float g_Hid[M_ * 2 * D_];
__device__ float g_KV[KV_ELEMS];
__device__ float g_Ks[KS_ELEMS];
__device__ __half g_WTh [4 * D_ * D_];        // frag-major fp16 weights
__device__ __half g_w1Th[8 * 2 * D_ * D_];
__device__ __half g_w2Th[8 * D_ * 2 * D_];

// ================= mma helper =================
__device__ __forceinline__ void mma_f16(float d[4], const uint32_t a[4],
                                        uint32_t b0, uint32_t b1) {
    asm volatile(
        "mma.sync.aligned.m16n8k16.row.col.f32.f16.f16.f32 "
        "{%0,%1,%2,%3}, {%4,%5,%6,%7}, {%8,%9}, {%0,%1,%2,%3};\n"
        : "+f"(d[0]), "+f"(d[1]), "+f"(d[2]), "+f"(d[3])
        : "r"(a[0]), "r"(a[1]), "r"(a[2]), "r"(a[3]), "r"(b0), "r"(b1));
}

// ================= weight pack: [K,N] f32 -> frag-major fp16 =================
// u32-frag index within a 512B fragment = lane*4 + reg; lane = gid*4 + qid
// (conflict-free LDS.128 / coalesced LDG.128)
__device__ __forceinline__ void pack_one(const float* __restrict__ in,
                                         __half* __restrict__ out,
                                         int t, int K, int N)
{
    int k = t / N, n = t % N;
    int nblk = n >> 8, nloc = n & 255;
    int wn = nloc >> 5, j = (nloc >> 3) & 3, gid = nloc & 7;
    int p = j >> 1, jh = j & 1;
    int kch = k >> 5, kin = k & 31, kstep = kin >> 4, c16 = kin & 15;
    int qid = (c16 >> 1) & 3, kh = (c16 >> 3) & 1, h = c16 & 1;
    int lane = gid * 4 + qid;
    int NKCH = K >> 5;
    size_t idx = ((((((size_t)nblk * NKCH + kch) * 2 + kstep) * 8 + wn) * 2 + p) * 32
                  + lane) * 8 + jh * 4 + kh * 2 + h;
    out[idx] = __float2half_rn(in[t]);
}

__global__ void pack_all(const float* __restrict__ Wq, const float* __restrict__ Wk,
                         const float* __restrict__ Wv, const float* __restrict__ Wm,
                         const float* __restrict__ w1, const float* __restrict__ w2,
                         __half* __restrict__ WTh, __half* __restrict__ w1Th,
                         __half* __restrict__ w2Th)
{
    long idx = (long)blockIdx.x * 256 + threadIdx.x;
    const long S0 = 4L * 65536, S1 = 8L * 131072;
    if (idx < S0) {
        int which = (int)(idx >> 16), t = (int)(idx & 65535);
        const float* src = which == 0 ? Wq : which == 1 ? Wk : which == 2 ? Wv : Wm;
        pack_one(src, WTh + (long)which * 65536, t, 256, 256);
    } else if (idx < S0 + S1) {
        long i2 = idx - S0;
        int layer = (int)(i2 >> 17), t = (int)(i2 & 131071);
        pack_one(w1 + (long)layer * 131072, w1Th + (long)layer * 131072, t, 256, 512);
    } else {
        long i2 = idx - S0 - S1;
        int layer = (int)(i2 >> 17), t = (int)(i2 & 131071);
        pack_one(w2 + (long)layer * 131072, w2Th + (long)layer * 131072, t, 512, 256);
    }
}

// ================= fp16 tensor-core GEMM, barrier-free mainloop =================
enum { EPI_QK = 1, EPI_V = 2, EPI_RELU = 3, EPI_BIAS_LN = 5, EPI_LN_RES = 6 };

template<int EPI, int KCH>
__global__ __launch_bounds__(256, 2)
void gemm_f16(const float* __restrict__ A, const __half* __restrict__ Bp,
              const float* __restrict__ bias, const float* __restrict__ mask,
              const float* __restrict__ lng, const float* __restrict__ lnb,
              float* __restrict__ C, int N)
{
    constexpr int K = KCH * 32;
    extern __shared__ float sm[];
    uint32_t* As = (uint32_t*)sm;                  // KCH slots x 1024 u32 (A frags)
    float* sbias = sm + KCH * 1024;
    float* sg    = sbias + 256;
    float* sb    = sg + 256;
    float* red1 = sm;                 // epilogue scratch (reuses A region)
    float* red2 = sm + 512;
    float* smu  = sm + 1024;
    float* srs  = sm + 1088;

    const int tid = threadIdx.x;
    const int wn = tid >> 5, lane = tid & 31;
    const int gid = lane >> 2, qid = lane & 3;
    const int rowBase = blockIdx.y * BM;
    const int colBase = blockIdx.x * 256;

    if (EPI == EPI_QK || EPI == EPI_V || EPI == EPI_BIAS_LN)
        sbias[tid] = bias[colBase + tid];
    if (EPI == EPI_BIAS_LN || EPI == EPI_LN_RES) { sg[tid] = lng[tid]; sb[tid] = lnb[tid]; }

    // ---- stage FULL A tile (64 x K) as fp16 fragments, once ----
    {
        const int arow = tid >> 2, aq = tid & 3;
        const float* Aptr = A + (size_t)(rowBase + arow) * K + aq * 8;
        const int a_base = ((aq >> 1) * 4 + (arow >> 4)) * 128 + (arow & 7) * 16
                         + (aq & 1) * 2 + ((arow >> 3) & 1);
        #pragma unroll
        for (int c = 0; c < KCH; c++) {
            float4 v0 = *(const float4*)(Aptr + (size_t)c * 32);
            float4 v1 = *(const float4*)(Aptr + (size_t)c * 32 + 4);
            uint32_t* d = As + c * 1024 + a_base;
            const float* f0 = (const float*)&v0;
            const float* f1 = (const float*)&v1;
            #pragma unroll
            for (int q = 0; q < 2; q++) {
                __half2 h = __float22half2_rn(make_float2(f0[2*q], f0[2*q+1]));
                d[q * 4] = *(const uint32_t*)&h;
            }
            #pragma unroll
            for (int q = 0; q < 2; q++) {
                __half2 h = __float22half2_rn(make_float2(f1[2*q], f1[2*q+1]));
                d[(q + 2) * 4] = *(const uint32_t*)&h;
            }
        }
    }
    __syncthreads();

    // ---- mainloop: no barriers; B frags LDG'd directly (L2/L1 resident) ----
    float acc[4][4][4];
    #pragma unroll
    for (int mi = 0; mi < 4; mi++)
        #pragma unroll
        for (int j = 0; j < 4; j++)
            #pragma unroll
            for (int q = 0; q < 4; q++) acc[mi][j][q] = 0.f;

    const __half* Bch = Bp + (size_t)blockIdx.x * KCH * 8192
                        + (size_t)wn * 512 + lane * 8;
    const int lane4 = lane * 4;

    uint4 b0c, b1c;
    {
        const __half* s = Bch;
        b0c = *(const uint4*)(s);
        b1c = *(const uint4*)(s + 256);
    }
    #pragma unroll
    for (int kk = 0; kk < 2 * KCH; kk++) {
        uint4 b0n, b1n;
        {
            const int nk = (kk + 1 < 2 * KCH) ? kk + 1 : kk;
            const __half* s = Bch + (size_t)(nk >> 1) * 8192 + (nk & 1) * 4096;
            b0n = *(const uint4*)(s);
            b1n = *(const uint4*)(s + 256);
        }
        const uint32_t* as = As + (kk >> 1) * 1024 + (kk & 1) * 512;
        uint4 af[4];
        #pragma unroll
        for (int mi = 0; mi < 4; mi++)
            af[mi] = *(const uint4*)(as + mi * 128 + lane4);
        #pragma unroll
        for (int mi = 0; mi < 4; mi++) {
            const uint32_t a4[4] = {af[mi].x, af[mi].y, af[mi].z, af[mi].w};
            mma_f16(acc[mi][0], a4, b0c.x, b0c.y);
            mma_f16(acc[mi][1], a4, b0c.z, b0c.w);
            mma_f16(acc[mi][2], a4, b1c.x, b1c.y);
            mma_f16(acc[mi][3], a4, b1c.z, b1c.w);
        }
        b0c = b0n; b1c = b1n;
    }
    __syncthreads();   // A region free for epilogue scratch

    // ================= epilogue =================
    // element (mi,j,q): row = rowBase + mi*16 + (q>>1)*8 + gid
    //                   col = colBase + wn*32 + j*8 + qid*2 + (q&1)
    if (EPI == EPI_QK || EPI == EPI_V || EPI == EPI_BIAS_LN) {
        #pragma unroll
        for (int mi = 0; mi < 4; mi++)
            #pragma unroll
            for (int j = 0; j < 4; j++) {
                const int c = wn * 32 + j * 8 + qid * 2;
                acc[mi][j][0] += sbias[c];   acc[mi][j][1] += sbias[c + 1];
                acc[mi][j][2] += sbias[c];   acc[mi][j][3] += sbias[c + 1];
            }
    }
    if (EPI == EPI_QK || EPI == EPI_V) {
        float mk[4][2];
        #pragma unroll
        for (int mi = 0; mi < 4; mi++)
            #pragma unroll
            for (int r = 0; r < 2; r++)
                mk[mi][r] = mask[rowBase + mi * 16 + r * 8 + gid];
        #pragma unroll
        for (int mi = 0; mi < 4; mi++)
            #pragma unroll
            for (int j = 0; j < 4; j++)
                #pragma unroll
                for (int q = 0; q < 4; q++) {
                    float t = acc[mi][j][q];
                    if (EPI == EPI_QK) t = (t > 0.f) ? (t + 1.f) : expf(t);
                    acc[mi][j][q] = t * mk[mi][q >> 1];
                }
    }
    if (EPI == EPI_RELU) {
        #pragma unroll
        for (int mi = 0; mi < 4; mi++)
            #pragma unroll
            for (int j = 0; j < 4; j++)
                #pragma unroll
                for (int q = 0; q < 4; q++)
                    acc[mi][j][q] = acc[mi][j][q] > 0.f ? acc[mi][j][q] : 0.f;
    }

    if (EPI == EPI_BIAS_LN || EPI == EPI_LN_RES) {
        float s1[4][2], s2[4][2];
        #pragma unroll
        for (int mi = 0; mi < 4; mi++)
            #pragma unroll
            for (int r = 0; r < 2; r++) { s1[mi][r] = 0.f; s2[mi][r] = 0.f; }
        #pragma unroll
        for (int mi = 0; mi < 4; mi++)
            #pragma unroll
            for (int j = 0; j < 4; j++)
                #pragma unroll
                for (int q = 0; q < 4; q++) {
                    float v = acc[mi][j][q];
                    s1[mi][q >> 1] += v;
                    s2[mi][q >> 1] = fmaf(v, v, s2[mi][q >> 1]);
                }
        #pragma unroll
        for (int o = 1; o <= 2; o <<= 1)
            #pragma unroll
            for (int mi = 0; mi < 4; mi++)
                #pragma unroll
                for (int r = 0; r < 2; r++) {
                    s1[mi][r] += __shfl_xor_sync(0xffffffffu, s1[mi][r], o);
                    s2[mi][r] += __shfl_xor_sync(0xffffffffu, s2[mi][r], o);
                }
        if (qid == 0) {
            #pragma unroll
            for (int mi = 0; mi < 4; mi++)
                #pragma unroll
                for (int r = 0; r < 2; r++) {
                    int rl = mi * 16 + r * 8 + gid;
                    red1[rl * 8 + wn] = s1[mi][r];
                    red2[rl * 8 + wn] = s2[mi][r];
                }
        }
        __syncthreads();
        if (tid < 64) {
            float a = 0.f, b2 = 0.f;
            #pragma unroll
            for (int w = 0; w < 8; w++) { a += red1[tid * 8 + w]; b2 += red2[tid * 8 + w]; }
            float mu = a * (1.f / 256.f);
            float var = b2 * (1.f / 256.f) - mu * mu;
            smu[tid] = mu;
            srs[tid] = rsqrtf(var + EPS_LN);
        }
        __syncthreads();
        #pragma unroll
        for (int mi = 0; mi < 4; mi++)
            #pragma unroll
            for (int j = 0; j < 4; j++)
                #pragma unroll
                for (int q = 0; q < 4; q++) {
                    int rl = mi * 16 + (q >> 1) * 8 + gid;
                    int c  = wn * 32 + j * 8 + qid * 2 + (q & 1);
                    acc[mi][j][q] = (acc[mi][j][q] - smu[rl]) * srs[rl] * sg[c] + sb[c];
                }
    }

    // store
    #pragma unroll
    for (int mi = 0; mi < 4; mi++) {
        #pragma unroll
        for (int j = 0; j < 4; j++) {
            const int c  = colBase + wn * 32 + j * 8 + qid * 2;
            const int r0 = rowBase + mi * 16 + gid;
            const int r1 = r0 + 8;
            float2 v0 = make_float2(acc[mi][j][0], acc[mi][j][1]);
            float2 v1 = make_float2(acc[mi][j][2], acc[mi][j][3]);
            if (EPI == EPI_LN_RES) {
                float2 x0 = *(const float2*)&C[(size_t)r0 * N + c];
                float2 x1 = *(const float2*)&C[(size_t)r1 * N + c];
                v0.x += x0.x; v0.y += x0.y;
                v1.x += x1.x; v1.y += x1.y;
            }
            *(float2*)&C[(size_t)r0 * N + c] = v0;
            *(float2*)&C[(size_t)r1 * N + c] = v1;
        }
    }
}

// ================= zero KV / Ksum =================
__global__ void zero_kv(float* __restrict__ kv, float* __restrict__ ks)
{
    int i = blockIdx.x * 256 + threadIdx.x;
    if (i < KV_ELEMS) kv[i] = 0.f;
    if (i < KS_ELEMS) ks[i] = 0.f;
}

// ================= KV reduction =================
__global__ __launch_bounds__(256)
void kv_kernel(const float* __restrict__ Kp, const float* __restrict__ Vp,
               float* __restrict__ KV, float* __restrict__ Ks, int rowsPerSplit)
{
    const int bh = blockIdx.x;
    const int b = bh >> 3, h = bh & 7;
    const int l0 = blockIdx.y * rowsPerSplit;
    const int tid = threadIdx.x;
    const int lr = tid >> 5;
    const int ld = tid & 31;

    __shared__ float Kt[8][32];
    __shared__ float Vt[8][32];

    float a0 = 0.f, a1 = 0.f, a2 = 0.f, a3 = 0.f, ks = 0.f;

    for (int c = 0; c < rowsPerSplit; c += 8) {
        int l = l0 + c + lr;
        size_t base = ((size_t)b * L_ + l) * D_ + h * DIM_ + ld;
        Kt[lr][ld] = Kp[base];
        Vt[lr][ld] = Vp[base];
        __syncthreads();
        #pragma unroll
        for (int r = 0; r < 8; r++) {
            float kv = Kt[r][ld];
            a0 = fmaf(kv, Vt[r][lr +  0], a0);
            a1 = fmaf(kv, Vt[r][lr +  8], a1);
            a2 = fmaf(kv, Vt[r][lr + 16], a2);
            a3 = fmaf(kv, Vt[r][lr + 24], a3);
        }
        if (tid < 32) {
            #pragma unroll
            for (int r = 0; r < 8; r++) ks += Kt[r][tid];
        }
        __syncthreads();
    }

    float* kvb = KV + (size_t)bh * DIM_ * DIM_;
    atomicAdd(&kvb[(lr +  0) * DIM_ + ld], a0);
    atomicAdd(&kvb[(lr +  8) * DIM_ + ld], a1);
    atomicAdd(&kvb[(lr + 16) * DIM_ + ld], a2);
    atomicAdd(&kvb[(lr + 24) * DIM_ + ld], a3);
    if (tid < 32) atomicAdd(&Ks[bh * DIM_ + tid], ks);
}

// ================= attention apply =================
__global__ __launch_bounds__(256)
void attn_apply(const float* __restrict__ Q, const float* __restrict__ KV,
                const float* __restrict__ Ks, float* __restrict__ Out)
{
    __shared__ float sKV[H_ * DIM_ * DIM_];
    __shared__ float sKs[H_ * DIM_];
    const int b = blockIdx.y;
    const int tid = threadIdx.x;

    for (int i = tid; i < H_ * DIM_ * DIM_; i += 256)
        sKV[i] = KV[(size_t)b * H_ * DIM_ * DIM_ + i];
    if (tid < H_ * DIM_) sKs[tid] = Ks[b * H_ * DIM_ + tid];
    __syncthreads();

    const int token = blockIdx.x * 256 + tid;
    if (token >= L_) return;
    const size_t row = (size_t)b * L_ + token;
    const float* q = Q + row * D_;
    float* o = Out + row * D_;

    for (int h = 0; h < H_; h++) {
        float qr[DIM_];
        #pragma unroll
        for (int d = 0; d < DIM_; d++) qr[d] = q[h * DIM_ + d];
        float s = 0.f;
        #pragma unroll
        for (int d = 0; d < DIM_; d++) s = fmaf(qr[d], sKs[h * DIM_ + d], s);
        float z = 1.f / (s + EPS_ATTN);
        const float* kvh = &sKV[h * DIM_ * DIM_];
        #pragma unroll 4
        for (int m = 0; m < DIM_; m++) {
            float acc = 0.f;
            #pragma unroll
            for (int d = 0; d < DIM_; d++) acc = fmaf(kvh[m * DIM_ + d], qr[d], acc);
            o[h * DIM_ + m] = acc * z;
        }
    }
}

// ================= host orchestration =================
namespace {

struct Ptrs {
    float *x0, *x1, *Q, *K, *V, *A, *Msg, *Hid, *KV, *Ks;
    __half *WTh, *w1Th, *w2Th;
};

void run_layer(float* x, const float* src, const float* xm, const float* sm,
               const __half* WqP, const float* bq, const __half* WkP, const float* bk,
               const __half* WvP, const float* bv, const __half* WmP, const float* bm,
               const __half* w1P, const __half* w2P, const float* g1, const float* b1,
               const float* g2, const float* b2, const Ptrs& p)
{
    dim3 g1d(1, M_ / BM);   // (1, 600)
    dim3 g2d(2, M_ / BM);   // (2, 600)

    zero_kv<<<(KV_ELEMS + 255) / 256, 256>>>(p.KV, p.Ks);
    gemm_f16<EPI_QK, 8><<<g1d, 256, SMEM_K8>>>(x,   WqP, bq, xm, nullptr, nullptr, p.Q, 256);
    gemm_f16<EPI_QK, 8><<<g1d, 256, SMEM_K8>>>(src, WkP, bk, sm, nullptr, nullptr, p.K, 256);
    gemm_f16<EPI_V , 8><<<g1d, 256, SMEM_K8>>>(src, WvP, bv, sm, nullptr, nullptr, p.V, 256);
    kv_kernel<<<dim3(B_ * H_, 20), 256>>>(p.K, p.V, p.KV, p.Ks, L_ / 20);
    attn_apply<<<dim3((L_ + 255) / 256, B_), 256>>>(p.Q, p.KV, p.Ks, p.A);

    gemm_f16<EPI_BIAS_LN, 8><<<g1d, 256, SMEM_K8>>>(p.A,   WmP, bm, nullptr, g1, b1, p.Msg, 256);
    gemm_f16<EPI_RELU  , 8><<<g2d, 256, SMEM_K8>>>(p.Msg, w1P, nullptr, nullptr, nullptr, nullptr, p.Hid, 512);
    gemm_f16<EPI_LN_RES, 16><<<g1d, 256, SMEM_K16>>>(p.Hid, w2P, nullptr, nullptr, g2, b2, x, 256);
}

} // namespace

extern "C" void kernel_launch(void* const* d_in, const int* in_sizes, int n_in,
                              void* d_out, int out_size)
{
    const float* desc0 = (const float*)d_in[0];
    const float* desc1 = (const float*)d_in[1];
    const float* mask0 = (const float*)d_in[2];
    const float* mask1 = (const float*)d_in[3];
    const float* Wq = (const float*)d_in[4];
    const float* bq = (const float*)d_in[5];
    const float* Wk = (const float*)d_in[6];
    const float* bk = (const float*)d_in[7];
    const float* Wv = (const float*)d_in[8];
    const float* bv = (const float*)d_in[9];
    const float* Wm = (const float*)d_in[10];
    const float* bm = (const float*)d_in[11];
    const float* w1 = (const float*)d_in[12];
    const float* w2 = (const float*)d_in[13];
    const float* g1 = (const float*)d_in[14];
    const float* b1 = (const float*)d_in[15];
    const float* g2 = (const float*)d_in[16];
    const float* b2 = (const float*)d_in[17];

    Ptrs p;
    cudaGetSymbolAddress((void**)&p.x0,  g_x0);
    cudaGetSymbolAddress((void**)&p.x1,  g_x1);
    cudaGetSymbolAddress((void**)&p.Q,   g_Q);
    cudaGetSymbolAddress((void**)&p.K,   g_K);
    cudaGetSymbolAddress((void**)&p.V,   g_V);
    cudaGetSymbolAddress((void**)&p.A,   g_A);
    cudaGetSymbolAddress((void**)&p.Msg, g_Msg);
    cudaGetSymbolAddress((void**)&p.Hid, g_Hid);
    cudaGetSymbolAddress((void**)&p.KV,  g_KV);
    cudaGetSymbolAddress((void**)&p.Ks,  g_Ks);
    cudaGetSymbolAddress((void**)&p.WTh,  g_WTh);
    cudaGetSymbolAddress((void**)&p.w1Th, g_w1Th);
    cudaGetSymbolAddress((void**)&p.w2Th, g_w2Th);

    cudaFuncSetAttribute((const void*)gemm_f16<EPI_QK, 8>,      cudaFuncAttributeMaxDynamicSharedMemorySize, SMEM_K8);
    cudaFuncSetAttribute((const void*)gemm_f16<EPI_V , 8>,      cudaFuncAttributeMaxDynamicSharedMemorySize, SMEM_K8);
    cudaFuncSetAttribute((const void*)gemm_f16<EPI_RELU, 8>,    cudaFuncAttributeMaxDynamicSharedMemorySize, SMEM_K8);
    cudaFuncSetAttribute((const void*)gemm_f16<EPI_BIAS_LN, 8>, cudaFuncAttributeMaxDynamicSharedMemorySize, SMEM_K8);
    cudaFuncSetAttribute((const void*)gemm_f16<EPI_LN_RES, 16>, cudaFuncAttributeMaxDynamicSharedMemorySize, SMEM_K16);

    // ---- one-time weight packing ----
    pack_all<<<(4 * 65536 + 2 * 8 * 131072) / 256, 256>>>(Wq, Wk, Wv, Wm, w1, w2,
                                                          p.WTh, p.w1Th, p.w2Th);

    const size_t tensorBytes = (size_t)M_ * D_ * sizeof(float);
    cudaMemcpyAsync(p.x0, desc0, tensorBytes, cudaMemcpyDeviceToDevice);
    cudaMemcpyAsync(p.x1, desc1, tensorBytes, cudaMemcpyDeviceToDevice);

    const int w1sz = D_ * 2 * D_;
    const int w2sz = 2 * D_ * D_;

    for (int li = 0; li < 8; li++) {
        const __half* lw1 = p.w1Th + (size_t)li * w1sz;
        const __half* lw2 = p.w2Th + (size_t)li * w2sz;
        const float* lg1 = g1 + li * D_;
        const float* lb1 = b1 + li * D_;
        const float* lg2 = g2 + li * D_;
        const float* lb2 = b2 + li * D_;
        const __half* WqP = p.WTh + 0 * D_ * D_;
        const __half* WkP = p.WTh + 1 * D_ * D_;
        const __half* WvP = p.WTh + 2 * D_ * D_;
        const __half* WmP = p.WTh + 3 * D_ * D_;
        if ((li & 1) == 0) {
            run_layer(p.x0, p.x0, mask0, mask0, WqP, bq, WkP, bk, WvP, bv, WmP, bm,
                      lw1, lw2, lg1, lb1, lg2, lb2, p);
            run_layer(p.x1, p.x1, mask1, mask1, WqP, bq, WkP, bk, WvP, bv, WmP, bm,
                      lw1, lw2, lg1, lb1, lg2, lb2, p);
        } else {
            run_layer(p.x0, p.x1, mask0, mask1, WqP, bq, WkP, bk, WvP, bv, WmP, bm,
                      lw1, lw2, lg1, lb1, lg2, lb2, p);
            run_layer(p.x1, p.x0, mask1, mask0, WqP, bq, WkP, bk, WvP, bv, WmP, bm,
                      lw1, lw2, lg1, lb1, lg2, lb2, p);
        }
    }

    cudaMemcpyAsync((float*)d_out,                   p.x0, tensorBytes, cudaMemcpyDeviceToDevice);
    cudaMemcpyAsync((float*)d_out + (size_t)M_ * D_, p.x1, tensorBytes, cudaMemcpyDeviceToDevice);
}